// round 11
// baseline (speedup 1.0000x reference)
#include <cuda_runtime.h>
#include <cuda_fp16.h>
#include <cstdint>

// Problem constants (fixed by the dataset)
#define BB 4
#define NN 50000
#define RR 100000
#define EE 1600000
#define D1 32
#define D2 16
#define NEG 0.2f

// Bucket capacities (Poisson lambda=16 R-rows / 32 N-rows; overflow prob < 1e-25)
#define CAP_T1 128
#define CAP_X1 192
#define CAP_T2 128
#define CAP_P1 256

#define MW_R ((RR + 31) / 32)
#define MW_N ((NN + 31) / 32)

#define SCAN_T   (EE / 8)                  // 200000 scan threads (8 edges each)
#define SCAN_B   ((SCAN_T + 255) / 256)    // 782 scan blocks
#define H1_W     (NN * BB)                 // 200000 h1 rows
#define H1_B4    (H1_W / 32)               // 6250 h1 blocks (8 warps x 4 rows = 32 rows)
#define H1_CHUNK ((H1_B4 + 3) / 4)         // 1563 h1 blocks per scan kernel

// Bloom filters (first-level membership pre-check; tiny -> L1-broadcast loads)
#define BLT2_W 64     // 256 B, 2048 bits   (~64 set -> FP 3%)
#define BLH2_W 256    // 1 KB, 8192 bits    (~1K set -> FP 12%)

// ---------------- device scratch (zero-init at module load; left zeroed per call) ----
__device__ __half g_h1[NN * BB * D1];  // 12.8 MB  [n][b][32] fp16
__device__ float g_T1[RR * BB * D1];   // 51.2 MB  [r][b][32]
__device__ float g_h2[NN * BB * D2];   // 12.8 MB  [n][b][16]
__device__ float g_T2[RR * BB * D2];   // 25.6 MB  [r][b][16]

__device__ int  g_cntT1[RR], g_cntX1[NN], g_cntT2[RR], g_cntP1[2];
__device__ int2 g_bT1[RR * CAP_T1];    // (col, val)
__device__ int2 g_bX1[NN * CAP_X1];    // (col, coef)
__device__ int2 g_bT2[RR * CAP_T2];    // (col, val)
__device__ int2 g_bP1[2 * CAP_P1];     // (col, coef)

__device__ unsigned g_mT1[MW_R], g_mT2[MW_R], g_mH2[MW_N];   // exact bit flags
__device__ unsigned g_blT2[BLT2_W], g_blH2[BLH2_W];          // bloom pre-filters

// ---------------- h1 block: 8 warps x 4 rows (one node, 4 batches per warp) ----------
// sW loaded once per 32 rows (was: once per 8); 32 LDS/k shared across 4 rows.
__device__ __forceinline__ void h1_block(int hb, const float* __restrict__ x,
                                         const float* __restrict__ W1) {
    if (hb >= H1_B4) return;
    __shared__ float sW[D1 * D1];
    int t = threadIdx.x;
    for (int i = t; i < D1 * D1; i += 256) sW[i] = W1[i];
    __syncthreads();
    int lane = t & 31, wl = t >> 5;
    int w0 = hb * 32 + wl * 4;          // 4 consecutive rows = node n, batches 0..3
    int n = w0 >> 2;
    float xv0 = __ldg(&x[((size_t)0 * NN + n) * D1 + lane]);
    float xv1 = __ldg(&x[((size_t)1 * NN + n) * D1 + lane]);
    float xv2 = __ldg(&x[((size_t)2 * NN + n) * D1 + lane]);
    float xv3 = __ldg(&x[((size_t)3 * NN + n) * D1 + lane]);
    float a0 = 0.f, a1 = 0.f, a2 = 0.f, a3 = 0.f;
#pragma unroll
    for (int k = 0; k < D1; k++) {
        float wk = sW[k * D1 + lane];
        a0 = fmaf(__shfl_sync(0xffffffffu, xv0, k), wk, a0);
        a1 = fmaf(__shfl_sync(0xffffffffu, xv1, k), wk, a1);
        a2 = fmaf(__shfl_sync(0xffffffffu, xv2, k), wk, a2);
        a3 = fmaf(__shfl_sync(0xffffffffu, xv3, k), wk, a3);
    }
    g_h1[(size_t)(w0 + 0) * D1 + lane] = __float2half(a0);
    g_h1[(size_t)(w0 + 1) * D1 + lane] = __float2half(a1);
    g_h1[(size_t)(w0 + 2) * D1 + lane] = __float2half(a2);
    g_h1[(size_t)(w0 + 3) * D1 + lane] = __float2half(a3);
}

// ---------------- scan kernels: scan blocks first, then an h1 chunk ------------------
// S1: wi-edges into the 2 output nodes -> bP1 + mark mT2 + bloom blT2
__global__ void __launch_bounds__(256) k_s1(const int* __restrict__ wiRows,
        const int* __restrict__ wiCols, const float* __restrict__ wiVals,
        const float* __restrict__ diag2,
        const float* __restrict__ x, const float* __restrict__ W1) {
    if (blockIdx.x >= SCAN_B) { h1_block(blockIdx.x - SCAN_B, x, W1); return; }
    int t = blockIdx.x * 256 + threadIdx.x;
    if (t >= SCAN_T) return;
    int base = t * 8;
    int4 a = __ldg((const int4*)(wiRows + base));
    int4 b4 = __ldg((const int4*)(wiRows + base + 4));
    int r[8] = {a.x, a.y, a.z, a.w, b4.x, b4.y, b4.z, b4.w};
#pragma unroll
    for (int j = 0; j < 8; j++) {
        if (r[j] >= NN - 2) {
            int s = r[j] - (NN - 2);
            int e = base + j;
            int col = __ldg(&wiCols[e]);
            float coef = __ldg(&wiVals[e]) * __ldg(&diag2[col]);
            int slot = atomicAdd(&g_cntP1[s], 1);
            if (slot < CAP_P1) g_bP1[s * CAP_P1 + slot] = make_int2(col, __float_as_int(coef));
            atomicOr(&g_mT2[col >> 5], 1u << (col & 31));
            atomicOr(&g_blT2[(col >> 5) & (BLT2_W - 1)], 1u << (col & 31));
        }
    }
}

// S2: w-edges feeding mT2 rows -> bT2 + mark mH2 + bloom blH2
__global__ void __launch_bounds__(256) k_s2(const int* __restrict__ wRows,
        const int* __restrict__ wCols, const float* __restrict__ wVals,
        const float* __restrict__ x, const float* __restrict__ W1) {
    if (blockIdx.x >= SCAN_B) { h1_block(blockIdx.x - SCAN_B + H1_CHUNK, x, W1); return; }
    int t = blockIdx.x * 256 + threadIdx.x;
    if (t >= SCAN_T) return;
    int base = t * 8;
    int4 a = __ldg((const int4*)(wRows + base));
    int4 b4 = __ldg((const int4*)(wRows + base + 4));
    int r[8] = {a.x, a.y, a.z, a.w, b4.x, b4.y, b4.z, b4.w};
    unsigned bl[8];
#pragma unroll
    for (int j = 0; j < 8; j++) bl[j] = __ldg(&g_blT2[(r[j] >> 5) & (BLT2_W - 1)]);
#pragma unroll
    for (int j = 0; j < 8; j++) {
        if ((bl[j] >> (r[j] & 31)) & 1u) {
            if ((__ldg(&g_mT2[r[j] >> 5]) >> (r[j] & 31)) & 1u) {
                int e = base + j;
                int col = __ldg(&wCols[e]);
                int slot = atomicAdd(&g_cntT2[r[j]], 1);
                if (slot < CAP_T2)
                    g_bT2[r[j] * CAP_T2 + slot] = make_int2(col, __float_as_int(__ldg(&wVals[e])));
                atomicOr(&g_mH2[col >> 5], 1u << (col & 31));
                atomicOr(&g_blH2[(col >> 5) & (BLH2_W - 1)], 1u << (col & 31));
            }
        }
    }
}

// S3: wi-edges feeding mH2 nodes -> bX1 (coef = val*diag1) + mark mT1
__global__ void __launch_bounds__(256) k_s3(const int* __restrict__ wiRows,
        const int* __restrict__ wiCols, const float* __restrict__ wiVals,
        const float* __restrict__ diag1,
        const float* __restrict__ x, const float* __restrict__ W1) {
    if (blockIdx.x >= SCAN_B) { h1_block(blockIdx.x - SCAN_B + 2 * H1_CHUNK, x, W1); return; }
    int t = blockIdx.x * 256 + threadIdx.x;
    if (t >= SCAN_T) return;
    int base = t * 8;
    int4 a = __ldg((const int4*)(wiRows + base));
    int4 b4 = __ldg((const int4*)(wiRows + base + 4));
    int r[8] = {a.x, a.y, a.z, a.w, b4.x, b4.y, b4.z, b4.w};
    unsigned bl[8];
#pragma unroll
    for (int j = 0; j < 8; j++) bl[j] = __ldg(&g_blH2[(r[j] >> 5) & (BLH2_W - 1)]);
#pragma unroll
    for (int j = 0; j < 8; j++) {
        if ((bl[j] >> (r[j] & 31)) & 1u) {
            if ((__ldg(&g_mH2[r[j] >> 5]) >> (r[j] & 31)) & 1u) {
                int e = base + j;
                int col = __ldg(&wiCols[e]);
                float coef = __ldg(&wiVals[e]) * __ldg(&diag1[col]);
                int slot = atomicAdd(&g_cntX1[r[j]], 1);
                if (slot < CAP_X1)
                    g_bX1[r[j] * CAP_X1 + slot] = make_int2(col, __float_as_int(coef));
                atomicOr(&g_mT1[col >> 5], 1u << (col & 31));
            }
        }
    }
}

// S4: w-edges feeding mT1 rows -> bT1 (28% hit: stream cols+vals; no bloom useful)
__global__ void __launch_bounds__(256) k_s4(const int* __restrict__ wRows,
        const int* __restrict__ wCols, const float* __restrict__ wVals,
        const float* __restrict__ x, const float* __restrict__ W1) {
    if (blockIdx.x >= SCAN_B) { h1_block(blockIdx.x - SCAN_B + 3 * H1_CHUNK, x, W1); return; }
    int t = blockIdx.x * 256 + threadIdx.x;
    if (t >= SCAN_T) return;
    int base = t * 8;
    int4 a = __ldg((const int4*)(wRows + base));
    int4 b4 = __ldg((const int4*)(wRows + base + 4));
    int4 c0 = __ldg((const int4*)(wCols + base));
    int4 c1 = __ldg((const int4*)(wCols + base + 4));
    float4 v0 = __ldg((const float4*)(wVals + base));
    float4 v1 = __ldg((const float4*)(wVals + base + 4));
    int r[8] = {a.x, a.y, a.z, a.w, b4.x, b4.y, b4.z, b4.w};
    int cc[8] = {c0.x, c0.y, c0.z, c0.w, c1.x, c1.y, c1.z, c1.w};
    float vv[8] = {v0.x, v0.y, v0.z, v0.w, v1.x, v1.y, v1.z, v1.w};
    unsigned m[8];
#pragma unroll
    for (int j = 0; j < 8; j++) m[j] = __ldg(&g_mT1[r[j] >> 5]);
#pragma unroll
    for (int j = 0; j < 8; j++) {
        if ((m[j] >> (r[j] & 31)) & 1u) {
            int slot = atomicAdd(&g_cntT1[r[j]], 1);
            if (slot < CAP_T1)
                g_bT1[r[j] * CAP_T1 + slot] = make_int2(cc[j], __float_as_int(vv[j]));
        }
    }
}

// ---------------- T1[row] = sum_e v_e * h1[col_e]; one warp per row, full width ------
__global__ void __launch_bounds__(256) k_T1() {
    int w = (blockIdx.x * 256 + threadIdx.x) >> 5;
    if (w >= RR) return;
    int c = g_cntT1[w];
    if (c == 0) return;
    if (c > CAP_T1) c = CAP_T1;
    int lane = threadIdx.x & 31;
    int b = lane >> 3, q = lane & 7;
    const int2* bk = &g_bT1[w * CAP_T1];
    float4 acc = make_float4(0.f, 0.f, 0.f, 0.f);
    int k = 0;
    for (; k + 4 <= c; k += 4) {
        int2 e0 = __ldg(&bk[k]),     e1 = __ldg(&bk[k + 1]);
        int2 e2 = __ldg(&bk[k + 2]), e3 = __ldg(&bk[k + 3]);
        uint2 u0 = *(const uint2*)&g_h1[((size_t)e0.x * BB + b) * D1 + q * 4];
        uint2 u1 = *(const uint2*)&g_h1[((size_t)e1.x * BB + b) * D1 + q * 4];
        uint2 u2 = *(const uint2*)&g_h1[((size_t)e2.x * BB + b) * D1 + q * 4];
        uint2 u3 = *(const uint2*)&g_h1[((size_t)e3.x * BB + b) * D1 + q * 4];
        float v0 = __int_as_float(e0.y), v1 = __int_as_float(e1.y);
        float v2 = __int_as_float(e2.y), v3 = __int_as_float(e3.y);
        float2 a01, a23;
        a01 = __half22float2(*(__half2*)&u0.x); a23 = __half22float2(*(__half2*)&u0.y);
        acc.x = fmaf(v0, a01.x, acc.x); acc.y = fmaf(v0, a01.y, acc.y);
        acc.z = fmaf(v0, a23.x, acc.z); acc.w = fmaf(v0, a23.y, acc.w);
        a01 = __half22float2(*(__half2*)&u1.x); a23 = __half22float2(*(__half2*)&u1.y);
        acc.x = fmaf(v1, a01.x, acc.x); acc.y = fmaf(v1, a01.y, acc.y);
        acc.z = fmaf(v1, a23.x, acc.z); acc.w = fmaf(v1, a23.y, acc.w);
        a01 = __half22float2(*(__half2*)&u2.x); a23 = __half22float2(*(__half2*)&u2.y);
        acc.x = fmaf(v2, a01.x, acc.x); acc.y = fmaf(v2, a01.y, acc.y);
        acc.z = fmaf(v2, a23.x, acc.z); acc.w = fmaf(v2, a23.y, acc.w);
        a01 = __half22float2(*(__half2*)&u3.x); a23 = __half22float2(*(__half2*)&u3.y);
        acc.x = fmaf(v3, a01.x, acc.x); acc.y = fmaf(v3, a01.y, acc.y);
        acc.z = fmaf(v3, a23.x, acc.z); acc.w = fmaf(v3, a23.y, acc.w);
    }
    for (; k < c; k++) {
        int2 e0 = __ldg(&bk[k]);
        float v = __int_as_float(e0.y);
        uint2 u0 = *(const uint2*)&g_h1[((size_t)e0.x * BB + b) * D1 + q * 4];
        float2 a01 = __half22float2(*(__half2*)&u0.x);
        float2 a23 = __half22float2(*(__half2*)&u0.y);
        acc.x = fmaf(v, a01.x, acc.x); acc.y = fmaf(v, a01.y, acc.y);
        acc.z = fmaf(v, a23.x, acc.z); acc.w = fmaf(v, a23.y, acc.w);
    }
    *(float4*)&g_T1[((size_t)w * BB + b) * D1 + q * 4] = acc;
}

// ---------------- fused x1 + h2, one warp per node, full width -----------------------
__global__ void __launch_bounds__(256) k_x1h2(const float* __restrict__ W2) {
    __shared__ float sW[D1 * D2];
    __shared__ float sX[8][BB * D1];
    int t = threadIdx.x;
    for (int i = t; i < D1 * D2; i += 256) sW[i] = W2[i];
    __syncthreads();
    int node = (blockIdx.x * 256 + t) >> 5;
    if (node >= NN) return;
    int c = g_cntX1[node];
    if (c == 0) return;
    if (c > CAP_X1) c = CAP_X1;
    int lane = t & 31;
    int wlocal = t >> 5;
    int b = lane >> 3, q = lane & 7;
    const int2* bk = &g_bX1[node * CAP_X1];
    float4 acc = make_float4(0.f, 0.f, 0.f, 0.f);
    int k = 0;
    for (; k + 2 <= c; k += 2) {
        int2 e0 = __ldg(&bk[k]), e1 = __ldg(&bk[k + 1]);
        float4 t0 = *(const float4*)&g_T1[((size_t)e0.x * BB + b) * D1 + q * 4];
        float4 t1 = *(const float4*)&g_T1[((size_t)e1.x * BB + b) * D1 + q * 4];
        float v0 = __int_as_float(e0.y), v1 = __int_as_float(e1.y);
        acc.x = fmaf(v0, t0.x, acc.x); acc.y = fmaf(v0, t0.y, acc.y);
        acc.z = fmaf(v0, t0.z, acc.z); acc.w = fmaf(v0, t0.w, acc.w);
        acc.x = fmaf(v1, t1.x, acc.x); acc.y = fmaf(v1, t1.y, acc.y);
        acc.z = fmaf(v1, t1.z, acc.z); acc.w = fmaf(v1, t1.w, acc.w);
    }
    for (; k < c; k++) {
        int2 e0 = __ldg(&bk[k]);
        float v = __int_as_float(e0.y);
        float4 tv = *(const float4*)&g_T1[((size_t)e0.x * BB + b) * D1 + q * 4];
        acc.x = fmaf(v, tv.x, acc.x); acc.y = fmaf(v, tv.y, acc.y);
        acc.z = fmaf(v, tv.z, acc.z); acc.w = fmaf(v, tv.w, acc.w);
    }
    acc.x = acc.x > 0.f ? acc.x : NEG * acc.x;
    acc.y = acc.y > 0.f ? acc.y : NEG * acc.y;
    acc.z = acc.z > 0.f ? acc.z : NEG * acc.z;
    acc.w = acc.w > 0.f ? acc.w : NEG * acc.w;
    *(float4*)&sX[wlocal][b * D1 + q * 4] = acc;
    __syncwarp();
    int j = lane & 7;
    const float* xr = &sX[wlocal][b * D1];
    float a0 = 0.f, a1 = 0.f;
#pragma unroll
    for (int kk = 0; kk < D1; kk++) {
        float xv = xr[kk];
        a0 = fmaf(xv, sW[kk * D2 + j], a0);
        a1 = fmaf(xv, sW[kk * D2 + j + 8], a1);
    }
    g_h2[((size_t)node * BB + b) * D2 + j] = a0;
    g_h2[((size_t)node * BB + b) * D2 + j + 8] = a1;
}

// ---------------- T2[row] = sum_e v_e * h2[col_e]; one warp per row, full width ------
__global__ void __launch_bounds__(256) k_T2() {
    int w = (blockIdx.x * 256 + threadIdx.x) >> 5;
    if (w >= RR) return;
    int c = g_cntT2[w];
    if (c == 0) return;
    if (c > CAP_T2) c = CAP_T2;
    int lane = threadIdx.x & 31;
    if (lane >= 16) return;
    int b = lane >> 2, q = lane & 3;
    const int2* bk = &g_bT2[w * CAP_T2];
    float4 acc = make_float4(0.f, 0.f, 0.f, 0.f);
    for (int k = 0; k < c; k++) {
        int2 e0 = __ldg(&bk[k]);
        float v = __int_as_float(e0.y);
        float4 h = *(const float4*)&g_h2[((size_t)e0.x * BB + b) * D2 + q * 4];
        acc.x = fmaf(v, h.x, acc.x); acc.y = fmaf(v, h.y, acc.y);
        acc.z = fmaf(v, h.z, acc.z); acc.w = fmaf(v, h.w, acc.w);
    }
    *(float4*)&g_T2[((size_t)w * BB + b) * D2 + q * 4] = acc;
}

// ---------------- final heads + tail zeroing (state left clean for next call) --------
__global__ void __launch_bounds__(256) k_outz(const float* __restrict__ rw1,
        const float* __restrict__ rb1, const float* __restrict__ rw2,
        const float* __restrict__ rb2, float* __restrict__ out) {
    if (blockIdx.x == 0) {
        int warp = threadIdx.x >> 5;   // 8 warps: b = warp&3, s = warp>>2
        int lane = threadIdx.x & 31;
        int b = warp & 3, s = warp >> 2;
        int c = g_cntP1[s]; if (c > CAP_P1) c = CAP_P1;
        float acc = 0.f;
        for (int i = 0; i < c; i++) {
            int2 e = g_bP1[s * CAP_P1 + i];
            float coef = __int_as_float(e.y);
            if (lane < D2) acc = fmaf(coef, g_T2[((size_t)e.x * BB + b) * D2 + lane], acc);
        }
        float v = acc > 0.f ? acc : NEG * acc;
        const float* w = s ? rw2 : rw1;
        float y = (lane < D2) ? v * w[lane] : 0.f;
#pragma unroll
        for (int o = 16; o > 0; o >>= 1) y += __shfl_xor_sync(0xffffffffu, y, o);
        if (lane == 0) out[b * 2 + s] = y + (s ? rb2[0] : rb1[0]);
        __syncthreads();                       // all warps done reading g_cntP1
        if (threadIdx.x < 2) g_cntP1[threadIdx.x] = 0;
        if (threadIdx.x >= 32 && threadIdx.x < 32 + BLT2_W) g_blT2[threadIdx.x - 32] = 0u;
    } else {
        int i0 = (blockIdx.x - 1) * 256 + threadIdx.x;
        const int stride = 64 * 256;
        for (int i = i0; i < RR; i += stride) { g_cntT1[i] = 0; g_cntT2[i] = 0; }
        for (int i = i0; i < NN; i += stride) g_cntX1[i] = 0;
        for (int i = i0; i < MW_R; i += stride) { g_mT1[i] = 0u; g_mT2[i] = 0u; }
        for (int i = i0; i < MW_N; i += stride) g_mH2[i] = 0u;
        for (int i = i0; i < BLH2_W; i += stride) g_blH2[i] = 0u;
    }
}

// ---------------- launch ----------------
extern "C" void kernel_launch(void* const* d_in, const int* in_sizes, int n_in,
                              void* d_out, int out_size) {
    const int*   wIdx   = (const int*)d_in[0];
    const float* wVal   = (const float*)d_in[1];
    const int*   wiIdx  = (const int*)d_in[2];
    const float* wiVal  = (const float*)d_in[3];
    const float* x      = (const float*)d_in[4];
    const float* W1     = (const float*)d_in[5];
    const float* diag1  = (const float*)d_in[6];
    const float* W2     = (const float*)d_in[7];
    const float* diag2  = (const float*)d_in[8];
    const float* rw1    = (const float*)d_in[9];
    const float* rb1    = (const float*)d_in[10];
    const float* rw2    = (const float*)d_in[11];
    const float* rb2    = (const float*)d_in[12];

    const int* wRows  = wIdx;
    const int* wCols  = wIdx + EE;
    const int* wiRows = wiIdx;
    const int* wiCols = wiIdx + EE;
    float* out = (float*)d_out;

    const int mixGrid = SCAN_B + H1_CHUNK;   // 782 + 1563

    k_s1<<<mixGrid, 256>>>(wiRows, wiCols, wiVal, diag2, x, W1);
    k_s2<<<mixGrid, 256>>>(wRows, wCols, wVal, x, W1);
    k_s3<<<mixGrid, 256>>>(wiRows, wiCols, wiVal, diag1, x, W1);
    k_s4<<<mixGrid, 256>>>(wRows, wCols, wVal, x, W1);
    k_T1<<<(RR * 32 + 255) / 256, 256>>>();
    k_x1h2<<<(NN * 32 + 255) / 256, 256>>>(W2);
    k_T2<<<(RR * 32 + 255) / 256, 256>>>();
    k_outz<<<65, 256>>>(rw1, rb1, rw2, rb2, out);
}

// round 12
// speedup vs baseline: 1.1484x; 1.1484x over previous
#include <cuda_runtime.h>
#include <cuda_fp16.h>
#include <cstdint>

// Problem constants (fixed by the dataset)
#define BB 4
#define NN 50000
#define RR 100000
#define EE 1600000
#define D1 32
#define D2 16
#define NEG 0.2f

// Bucket capacities (Poisson lambda=16 R-rows / 32 N-rows; overflow prob < 1e-25)
#define CAP_T1 128
#define CAP_X1 192
#define CAP_T2 128
#define CAP_P1 256

#define MW_R ((RR + 31) / 32)
#define MW_N ((NN + 31) / 32)

#define SCAN_T   (EE / 8)                  // 200000 scan threads (8 edges each)
#define SCAN_B   ((SCAN_T + 255) / 256)    // 782 scan blocks
#define H1_W     (NN * BB)                 // 200000 h1 warps (one per (n,b))
#define H1_B     ((H1_W + 7) / 8)          // 25000 h1 blocks (8 warps/block)

// Bloom filters (first-level membership pre-check; tiny -> L1-broadcast loads)
#define BLT2_W 64     // 256 B, 2048 bits   (~64 set -> FP 3%)
#define BLH2_W 256    // 1 KB, 8192 bits    (~1K set -> FP 12%)

// ---------------- device scratch (zero-init at module load; left zeroed per call) ----
__device__ __half g_h1[NN * BB * D1];  // 12.8 MB  [n][b][32] fp16
__device__ float g_T1[RR * BB * D1];   // 51.2 MB  [r][b][32]
__device__ float g_h2[NN * BB * D2];   // 12.8 MB  [n][b][16]
__device__ float g_T2[RR * BB * D2];   // 25.6 MB  [r][b][16]

__device__ int  g_cntT1[RR], g_cntX1[NN], g_cntT2[RR], g_cntP1[2];
__device__ int2 g_bT1[RR * CAP_T1];    // (col, val)
__device__ int2 g_bX1[NN * CAP_X1];    // (col, coef)
__device__ int2 g_bT2[RR * CAP_T2];    // (col, val)
__device__ int2 g_bP1[2 * CAP_P1];     // (col, coef)

__device__ unsigned g_mT1[MW_R], g_mT2[MW_R], g_mH2[MW_N];   // exact bit flags
__device__ unsigned g_blT2[BLT2_W], g_blH2[BLH2_W];          // bloom pre-filters

// ---------------- dedicated h1 kernel: 8 warps/block, one (n,b) row per warp --------
__global__ void __launch_bounds__(256) k_h1(const float* __restrict__ x,
                                            const float* __restrict__ W1) {
    __shared__ float sW[D1 * D1];
    int t = threadIdx.x;
    for (int i = t; i < D1 * D1; i += 256) sW[i] = W1[i];
    __syncthreads();
    int w = blockIdx.x * 8 + (t >> 5);
    if (w >= H1_W) return;
    int lane = t & 31;
    int n = w >> 2, b = w & 3;
    float xv = x[((size_t)b * NN + n) * D1 + lane];
    float acc = 0.f;
#pragma unroll
    for (int k = 0; k < D1; k++) {
        float xk = __shfl_sync(0xffffffffu, xv, k);
        acc = fmaf(xk, sW[k * D1 + lane], acc);
    }
    g_h1[(size_t)w * D1 + lane] = __float2half(acc);
}

// ---------------- scan kernels (pure, no h1 freight) ---------------------------------
// S1: wi-edges into the 2 output nodes -> bP1 + mark mT2 + bloom blT2
__global__ void __launch_bounds__(256) k_s1(const int* __restrict__ wiRows,
        const int* __restrict__ wiCols, const float* __restrict__ wiVals,
        const float* __restrict__ diag2) {
    int t = blockIdx.x * 256 + threadIdx.x;
    if (t >= SCAN_T) return;
    int base = t * 8;
    int4 a = __ldg((const int4*)(wiRows + base));
    int4 b4 = __ldg((const int4*)(wiRows + base + 4));
    int r[8] = {a.x, a.y, a.z, a.w, b4.x, b4.y, b4.z, b4.w};
#pragma unroll
    for (int j = 0; j < 8; j++) {
        if (r[j] >= NN - 2) {
            int s = r[j] - (NN - 2);
            int e = base + j;
            int col = __ldg(&wiCols[e]);
            float coef = __ldg(&wiVals[e]) * __ldg(&diag2[col]);
            int slot = atomicAdd(&g_cntP1[s], 1);
            if (slot < CAP_P1) g_bP1[s * CAP_P1 + slot] = make_int2(col, __float_as_int(coef));
            atomicOr(&g_mT2[col >> 5], 1u << (col & 31));
            atomicOr(&g_blT2[(col >> 5) & (BLT2_W - 1)], 1u << (col & 31));
        }
    }
}

// S2: w-edges feeding mT2 rows -> bT2 + mark mH2 + bloom blH2
__global__ void __launch_bounds__(256) k_s2(const int* __restrict__ wRows,
        const int* __restrict__ wCols, const float* __restrict__ wVals) {
    int t = blockIdx.x * 256 + threadIdx.x;
    if (t >= SCAN_T) return;
    int base = t * 8;
    int4 a = __ldg((const int4*)(wRows + base));
    int4 b4 = __ldg((const int4*)(wRows + base + 4));
    int r[8] = {a.x, a.y, a.z, a.w, b4.x, b4.y, b4.z, b4.w};
    unsigned bl[8];
#pragma unroll
    for (int j = 0; j < 8; j++) bl[j] = __ldg(&g_blT2[(r[j] >> 5) & (BLT2_W - 1)]);
#pragma unroll
    for (int j = 0; j < 8; j++) {
        if ((bl[j] >> (r[j] & 31)) & 1u) {
            if ((__ldg(&g_mT2[r[j] >> 5]) >> (r[j] & 31)) & 1u) {
                int e = base + j;
                int col = __ldg(&wCols[e]);
                int slot = atomicAdd(&g_cntT2[r[j]], 1);
                if (slot < CAP_T2)
                    g_bT2[r[j] * CAP_T2 + slot] = make_int2(col, __float_as_int(__ldg(&wVals[e])));
                atomicOr(&g_mH2[col >> 5], 1u << (col & 31));
                atomicOr(&g_blH2[(col >> 5) & (BLH2_W - 1)], 1u << (col & 31));
            }
        }
    }
}

// S3: wi-edges feeding mH2 nodes -> bX1 (coef = val*diag1) + mark mT1
__global__ void __launch_bounds__(256) k_s3(const int* __restrict__ wiRows,
        const int* __restrict__ wiCols, const float* __restrict__ wiVals,
        const float* __restrict__ diag1) {
    int t = blockIdx.x * 256 + threadIdx.x;
    if (t >= SCAN_T) return;
    int base = t * 8;
    int4 a = __ldg((const int4*)(wiRows + base));
    int4 b4 = __ldg((const int4*)(wiRows + base + 4));
    int r[8] = {a.x, a.y, a.z, a.w, b4.x, b4.y, b4.z, b4.w};
    unsigned bl[8];
#pragma unroll
    for (int j = 0; j < 8; j++) bl[j] = __ldg(&g_blH2[(r[j] >> 5) & (BLH2_W - 1)]);
#pragma unroll
    for (int j = 0; j < 8; j++) {
        if ((bl[j] >> (r[j] & 31)) & 1u) {
            if ((__ldg(&g_mH2[r[j] >> 5]) >> (r[j] & 31)) & 1u) {
                int e = base + j;
                int col = __ldg(&wiCols[e]);
                float coef = __ldg(&wiVals[e]) * __ldg(&diag1[col]);
                int slot = atomicAdd(&g_cntX1[r[j]], 1);
                if (slot < CAP_X1)
                    g_bX1[r[j] * CAP_X1 + slot] = make_int2(col, __float_as_int(coef));
                atomicOr(&g_mT1[col >> 5], 1u << (col & 31));
            }
        }
    }
}

// S4: w-edges feeding mT1 rows -> bT1 (28% hit: stream cols+vals; no bloom useful)
__global__ void __launch_bounds__(256) k_s4(const int* __restrict__ wRows,
        const int* __restrict__ wCols, const float* __restrict__ wVals) {
    int t = blockIdx.x * 256 + threadIdx.x;
    if (t >= SCAN_T) return;
    int base = t * 8;
    int4 a = __ldg((const int4*)(wRows + base));
    int4 b4 = __ldg((const int4*)(wRows + base + 4));
    int4 c0 = __ldg((const int4*)(wCols + base));
    int4 c1 = __ldg((const int4*)(wCols + base + 4));
    float4 v0 = __ldg((const float4*)(wVals + base));
    float4 v1 = __ldg((const float4*)(wVals + base + 4));
    int r[8] = {a.x, a.y, a.z, a.w, b4.x, b4.y, b4.z, b4.w};
    int cc[8] = {c0.x, c0.y, c0.z, c0.w, c1.x, c1.y, c1.z, c1.w};
    float vv[8] = {v0.x, v0.y, v0.z, v0.w, v1.x, v1.y, v1.z, v1.w};
    unsigned m[8];
#pragma unroll
    for (int j = 0; j < 8; j++) m[j] = __ldg(&g_mT1[r[j] >> 5]);
#pragma unroll
    for (int j = 0; j < 8; j++) {
        if ((m[j] >> (r[j] & 31)) & 1u) {
            int slot = atomicAdd(&g_cntT1[r[j]], 1);
            if (slot < CAP_T1)
                g_bT1[r[j] * CAP_T1 + slot] = make_int2(cc[j], __float_as_int(vv[j]));
        }
    }
}

// ---------------- T1[row] = sum_e v_e * h1[col_e]; one warp per row, full width ------
__global__ void __launch_bounds__(256) k_T1() {
    int w = (blockIdx.x * 256 + threadIdx.x) >> 5;
    if (w >= RR) return;
    int c = g_cntT1[w];
    if (c == 0) return;
    if (c > CAP_T1) c = CAP_T1;
    int lane = threadIdx.x & 31;
    int b = lane >> 3, q = lane & 7;
    const int2* bk = &g_bT1[w * CAP_T1];
    float4 acc = make_float4(0.f, 0.f, 0.f, 0.f);
    int k = 0;
    for (; k + 4 <= c; k += 4) {
        int2 e0 = __ldg(&bk[k]),     e1 = __ldg(&bk[k + 1]);
        int2 e2 = __ldg(&bk[k + 2]), e3 = __ldg(&bk[k + 3]);
        uint2 u0 = *(const uint2*)&g_h1[((size_t)e0.x * BB + b) * D1 + q * 4];
        uint2 u1 = *(const uint2*)&g_h1[((size_t)e1.x * BB + b) * D1 + q * 4];
        uint2 u2 = *(const uint2*)&g_h1[((size_t)e2.x * BB + b) * D1 + q * 4];
        uint2 u3 = *(const uint2*)&g_h1[((size_t)e3.x * BB + b) * D1 + q * 4];
        float v0 = __int_as_float(e0.y), v1 = __int_as_float(e1.y);
        float v2 = __int_as_float(e2.y), v3 = __int_as_float(e3.y);
        float2 a01, a23;
        a01 = __half22float2(*(__half2*)&u0.x); a23 = __half22float2(*(__half2*)&u0.y);
        acc.x = fmaf(v0, a01.x, acc.x); acc.y = fmaf(v0, a01.y, acc.y);
        acc.z = fmaf(v0, a23.x, acc.z); acc.w = fmaf(v0, a23.y, acc.w);
        a01 = __half22float2(*(__half2*)&u1.x); a23 = __half22float2(*(__half2*)&u1.y);
        acc.x = fmaf(v1, a01.x, acc.x); acc.y = fmaf(v1, a01.y, acc.y);
        acc.z = fmaf(v1, a23.x, acc.z); acc.w = fmaf(v1, a23.y, acc.w);
        a01 = __half22float2(*(__half2*)&u2.x); a23 = __half22float2(*(__half2*)&u2.y);
        acc.x = fmaf(v2, a01.x, acc.x); acc.y = fmaf(v2, a01.y, acc.y);
        acc.z = fmaf(v2, a23.x, acc.z); acc.w = fmaf(v2, a23.y, acc.w);
        a01 = __half22float2(*(__half2*)&u3.x); a23 = __half22float2(*(__half2*)&u3.y);
        acc.x = fmaf(v3, a01.x, acc.x); acc.y = fmaf(v3, a01.y, acc.y);
        acc.z = fmaf(v3, a23.x, acc.z); acc.w = fmaf(v3, a23.y, acc.w);
    }
    for (; k < c; k++) {
        int2 e0 = __ldg(&bk[k]);
        float v = __int_as_float(e0.y);
        uint2 u0 = *(const uint2*)&g_h1[((size_t)e0.x * BB + b) * D1 + q * 4];
        float2 a01 = __half22float2(*(__half2*)&u0.x);
        float2 a23 = __half22float2(*(__half2*)&u0.y);
        acc.x = fmaf(v, a01.x, acc.x); acc.y = fmaf(v, a01.y, acc.y);
        acc.z = fmaf(v, a23.x, acc.z); acc.w = fmaf(v, a23.y, acc.w);
    }
    *(float4*)&g_T1[((size_t)w * BB + b) * D1 + q * 4] = acc;
}

// ---------------- fused x1 + h2, one warp per node, full width -----------------------
__global__ void __launch_bounds__(256) k_x1h2(const float* __restrict__ W2) {
    __shared__ float sW[D1 * D2];
    __shared__ float sX[8][BB * D1];
    int t = threadIdx.x;
    for (int i = t; i < D1 * D2; i += 256) sW[i] = W2[i];
    __syncthreads();
    int node = (blockIdx.x * 256 + t) >> 5;
    if (node >= NN) return;
    int c = g_cntX1[node];
    if (c == 0) return;
    if (c > CAP_X1) c = CAP_X1;
    int lane = t & 31;
    int wlocal = t >> 5;
    int b = lane >> 3, q = lane & 7;
    const int2* bk = &g_bX1[node * CAP_X1];
    float4 acc = make_float4(0.f, 0.f, 0.f, 0.f);
    int k = 0;
    for (; k + 2 <= c; k += 2) {
        int2 e0 = __ldg(&bk[k]), e1 = __ldg(&bk[k + 1]);
        float4 t0 = *(const float4*)&g_T1[((size_t)e0.x * BB + b) * D1 + q * 4];
        float4 t1 = *(const float4*)&g_T1[((size_t)e1.x * BB + b) * D1 + q * 4];
        float v0 = __int_as_float(e0.y), v1 = __int_as_float(e1.y);
        acc.x = fmaf(v0, t0.x, acc.x); acc.y = fmaf(v0, t0.y, acc.y);
        acc.z = fmaf(v0, t0.z, acc.z); acc.w = fmaf(v0, t0.w, acc.w);
        acc.x = fmaf(v1, t1.x, acc.x); acc.y = fmaf(v1, t1.y, acc.y);
        acc.z = fmaf(v1, t1.z, acc.z); acc.w = fmaf(v1, t1.w, acc.w);
    }
    for (; k < c; k++) {
        int2 e0 = __ldg(&bk[k]);
        float v = __int_as_float(e0.y);
        float4 tv = *(const float4*)&g_T1[((size_t)e0.x * BB + b) * D1 + q * 4];
        acc.x = fmaf(v, tv.x, acc.x); acc.y = fmaf(v, tv.y, acc.y);
        acc.z = fmaf(v, tv.z, acc.z); acc.w = fmaf(v, tv.w, acc.w);
    }
    acc.x = acc.x > 0.f ? acc.x : NEG * acc.x;
    acc.y = acc.y > 0.f ? acc.y : NEG * acc.y;
    acc.z = acc.z > 0.f ? acc.z : NEG * acc.z;
    acc.w = acc.w > 0.f ? acc.w : NEG * acc.w;
    *(float4*)&sX[wlocal][b * D1 + q * 4] = acc;
    __syncwarp();
    int j = lane & 7;
    const float* xr = &sX[wlocal][b * D1];
    float a0 = 0.f, a1 = 0.f;
#pragma unroll
    for (int kk = 0; kk < D1; kk++) {
        float xv = xr[kk];
        a0 = fmaf(xv, sW[kk * D2 + j], a0);
        a1 = fmaf(xv, sW[kk * D2 + j + 8], a1);
    }
    g_h2[((size_t)node * BB + b) * D2 + j] = a0;
    g_h2[((size_t)node * BB + b) * D2 + j + 8] = a1;
}

// ---------------- T2[row] = sum_e v_e * h2[col_e]; one warp per row, full width ------
__global__ void __launch_bounds__(256) k_T2() {
    int w = (blockIdx.x * 256 + threadIdx.x) >> 5;
    if (w >= RR) return;
    int c = g_cntT2[w];
    if (c == 0) return;
    if (c > CAP_T2) c = CAP_T2;
    int lane = threadIdx.x & 31;
    if (lane >= 16) return;
    int b = lane >> 2, q = lane & 3;
    const int2* bk = &g_bT2[w * CAP_T2];
    float4 acc = make_float4(0.f, 0.f, 0.f, 0.f);
    for (int k = 0; k < c; k++) {
        int2 e0 = __ldg(&bk[k]);
        float v = __int_as_float(e0.y);
        float4 h = *(const float4*)&g_h2[((size_t)e0.x * BB + b) * D2 + q * 4];
        acc.x = fmaf(v, h.x, acc.x); acc.y = fmaf(v, h.y, acc.y);
        acc.z = fmaf(v, h.z, acc.z); acc.w = fmaf(v, h.w, acc.w);
    }
    *(float4*)&g_T2[((size_t)w * BB + b) * D2 + q * 4] = acc;
}

// ---------------- final heads + tail zeroing (state left clean for next call) --------
__global__ void __launch_bounds__(256) k_outz(const float* __restrict__ rw1,
        const float* __restrict__ rb1, const float* __restrict__ rw2,
        const float* __restrict__ rb2, float* __restrict__ out) {
    if (blockIdx.x == 0) {
        int warp = threadIdx.x >> 5;   // 8 warps: b = warp&3, s = warp>>2
        int lane = threadIdx.x & 31;
        int b = warp & 3, s = warp >> 2;
        int c = g_cntP1[s]; if (c > CAP_P1) c = CAP_P1;
        float acc = 0.f;
        for (int i = 0; i < c; i++) {
            int2 e = g_bP1[s * CAP_P1 + i];
            float coef = __int_as_float(e.y);
            if (lane < D2) acc = fmaf(coef, g_T2[((size_t)e.x * BB + b) * D2 + lane], acc);
        }
        float v = acc > 0.f ? acc : NEG * acc;
        const float* w = s ? rw2 : rw1;
        float y = (lane < D2) ? v * w[lane] : 0.f;
#pragma unroll
        for (int o = 16; o > 0; o >>= 1) y += __shfl_xor_sync(0xffffffffu, y, o);
        if (lane == 0) out[b * 2 + s] = y + (s ? rb2[0] : rb1[0]);
        __syncthreads();                       // all warps done reading g_cntP1
        if (threadIdx.x < 2) g_cntP1[threadIdx.x] = 0;
        if (threadIdx.x >= 32 && threadIdx.x < 32 + BLT2_W) g_blT2[threadIdx.x - 32] = 0u;
    } else {
        int i0 = (blockIdx.x - 1) * 256 + threadIdx.x;
        const int stride = 64 * 256;
        for (int i = i0; i < RR; i += stride) { g_cntT1[i] = 0; g_cntT2[i] = 0; }
        for (int i = i0; i < NN; i += stride) g_cntX1[i] = 0;
        for (int i = i0; i < MW_R; i += stride) { g_mT1[i] = 0u; g_mT2[i] = 0u; }
        for (int i = i0; i < MW_N; i += stride) g_mH2[i] = 0u;
        for (int i = i0; i < BLH2_W; i += stride) g_blH2[i] = 0u;
    }
}

// ---------------- launch ----------------
extern "C" void kernel_launch(void* const* d_in, const int* in_sizes, int n_in,
                              void* d_out, int out_size) {
    const int*   wIdx   = (const int*)d_in[0];
    const float* wVal   = (const float*)d_in[1];
    const int*   wiIdx  = (const int*)d_in[2];
    const float* wiVal  = (const float*)d_in[3];
    const float* x      = (const float*)d_in[4];
    const float* W1     = (const float*)d_in[5];
    const float* diag1  = (const float*)d_in[6];
    const float* W2     = (const float*)d_in[7];
    const float* diag2  = (const float*)d_in[8];
    const float* rw1    = (const float*)d_in[9];
    const float* rb1    = (const float*)d_in[10];
    const float* rw2    = (const float*)d_in[11];
    const float* rb2    = (const float*)d_in[12];

    const int* wRows  = wIdx;
    const int* wCols  = wIdx + EE;
    const int* wiRows = wiIdx;
    const int* wiCols = wiIdx + EE;
    float* out = (float*)d_out;

    k_h1<<<H1_B, 256>>>(x, W1);
    k_s1<<<SCAN_B, 256>>>(wiRows, wiCols, wiVal, diag2);
    k_s2<<<SCAN_B, 256>>>(wRows, wCols, wVal);
    k_s3<<<SCAN_B, 256>>>(wiRows, wiCols, wiVal, diag1);
    k_s4<<<SCAN_B, 256>>>(wRows, wCols, wVal);
    k_T1<<<(RR * 32 + 255) / 256, 256>>>();
    k_x1h2<<<(NN * 32 + 255) / 256, 256>>>(W2);
    k_T2<<<(RR * 32 + 255) / 256, 256>>>();
    k_outz<<<65, 256>>>(rw1, rb1, rw2, rb2, out);
}

// round 15
// speedup vs baseline: 1.5558x; 1.3548x over previous
#include <cuda_runtime.h>
#include <cuda_fp16.h>
#include <cstdint>

// Problem constants (fixed by the dataset)
#define BB 4
#define NN 50000
#define RR 100000
#define EE 1600000
#define D1 32
#define D2 16
#define NEG 0.2f

// Bucket capacities (Poisson lambda=16 R-rows / 32 N-rows; overflow prob < 1e-25)
#define CAP_T1 128
#define CAP_X1 192
#define CAP_T2 128
#define CAP_P1 256

#define MW_R ((RR + 31) / 32)
#define MW_N ((NN + 31) / 32)

#define SCAN_T   (EE / 8)                  // 200000 scan threads (8 edges each)
#define SCAN_B   ((SCAN_T + 255) / 256)    // 782 scan blocks
#define XH_W     (NN * BB)                 // 200000 conversion rows (one warp each)
#define XH_B     ((XH_W + 7) / 8)          // 25000 freight blocks (8 warps/block)
#define XH_CHUNK (XH_B / 4)                // 6250 freight blocks per scan kernel

// Bloom filters (first-level membership pre-check; tiny -> L1-broadcast loads)
#define BLT2_W 64     // 256 B, 2048 bits   (~64 set -> FP 3%)
#define BLH2_W 256    // 1 KB, 8192 bits    (~1K set -> FP 12%)

// ---------------- device scratch (zero-init at module load; left zeroed per call) ----
__device__ __half g_xh[NN * BB * D1];  // 12.8 MB  [n][b][32] fp16 copy of x
__device__ float g_T1[RR * BB * D1];   // 51.2 MB  [r][b][32]  (post-W1 values)
__device__ float g_h2[NN * BB * D2];   // 12.8 MB  [n][b][16]
__device__ float g_T2[RR * BB * D2];   // 25.6 MB  [r][b][16]

__device__ int  g_cntT1[RR], g_cntX1[NN], g_cntT2[RR], g_cntP1[2];
__device__ int2 g_bT1[RR * CAP_T1];    // (col, val)
__device__ int2 g_bX1[NN * CAP_X1];    // (col, coef)
__device__ int2 g_bT2[RR * CAP_T2];    // (col, val)
__device__ int2 g_bP1[2 * CAP_P1];     // (col, coef)

__device__ unsigned g_mT1[MW_R], g_mT2[MW_R], g_mH2[MW_N];   // exact bit flags
__device__ unsigned g_blT2[BLT2_W], g_blH2[BLH2_W];          // bloom pre-filters

// ---------------- freight: xh[n][b][:] = fp16(x[b][n][:]); 1 LDG + 1 STG per warp ----
__device__ __forceinline__ void xh_block(int vb, const float* __restrict__ x) {
    int w = vb * 8 + (threadIdx.x >> 5);
    if (w >= XH_W) return;
    int lane = threadIdx.x & 31;
    int n = w >> 2, b = w & 3;
    float xv = __ldg(&x[((size_t)b * NN + n) * D1 + lane]);
    g_xh[(size_t)w * D1 + lane] = __float2half(xv);
}

// ---------------- scan kernels: scan blocks first, then a conversion chunk -----------
// S1: wi-edges into the 2 output nodes -> bP1 + mark mT2 + bloom blT2
__global__ void __launch_bounds__(256) k_s1(const int* __restrict__ wiRows,
        const int* __restrict__ wiCols, const float* __restrict__ wiVals,
        const float* __restrict__ diag2, const float* __restrict__ x) {
    if (blockIdx.x >= SCAN_B) { xh_block(blockIdx.x - SCAN_B, x); return; }
    int t = blockIdx.x * 256 + threadIdx.x;
    if (t >= SCAN_T) return;
    int base = t * 8;
    int4 a = __ldg((const int4*)(wiRows + base));
    int4 b4 = __ldg((const int4*)(wiRows + base + 4));
    int r[8] = {a.x, a.y, a.z, a.w, b4.x, b4.y, b4.z, b4.w};
#pragma unroll
    for (int j = 0; j < 8; j++) {
        if (r[j] >= NN - 2) {
            int s = r[j] - (NN - 2);
            int e = base + j;
            int col = __ldg(&wiCols[e]);
            float coef = __ldg(&wiVals[e]) * __ldg(&diag2[col]);
            int slot = atomicAdd(&g_cntP1[s], 1);
            if (slot < CAP_P1) g_bP1[s * CAP_P1 + slot] = make_int2(col, __float_as_int(coef));
            atomicOr(&g_mT2[col >> 5], 1u << (col & 31));
            atomicOr(&g_blT2[(col >> 5) & (BLT2_W - 1)], 1u << (col & 31));
        }
    }
}

// S2: w-edges feeding mT2 rows -> bT2 + mark mH2 + bloom blH2
__global__ void __launch_bounds__(256) k_s2(const int* __restrict__ wRows,
        const int* __restrict__ wCols, const float* __restrict__ wVals,
        const float* __restrict__ x) {
    if (blockIdx.x >= SCAN_B) { xh_block(blockIdx.x - SCAN_B + XH_CHUNK, x); return; }
    int t = blockIdx.x * 256 + threadIdx.x;
    if (t >= SCAN_T) return;
    int base = t * 8;
    int4 a = __ldg((const int4*)(wRows + base));
    int4 b4 = __ldg((const int4*)(wRows + base + 4));
    int r[8] = {a.x, a.y, a.z, a.w, b4.x, b4.y, b4.z, b4.w};
    unsigned bl[8];
#pragma unroll
    for (int j = 0; j < 8; j++) bl[j] = __ldg(&g_blT2[(r[j] >> 5) & (BLT2_W - 1)]);
#pragma unroll
    for (int j = 0; j < 8; j++) {
        if ((bl[j] >> (r[j] & 31)) & 1u) {
            if ((__ldg(&g_mT2[r[j] >> 5]) >> (r[j] & 31)) & 1u) {
                int e = base + j;
                int col = __ldg(&wCols[e]);
                int slot = atomicAdd(&g_cntT2[r[j]], 1);
                if (slot < CAP_T2)
                    g_bT2[r[j] * CAP_T2 + slot] = make_int2(col, __float_as_int(__ldg(&wVals[e])));
                atomicOr(&g_mH2[col >> 5], 1u << (col & 31));
                atomicOr(&g_blH2[(col >> 5) & (BLH2_W - 1)], 1u << (col & 31));
            }
        }
    }
}

// S3: wi-edges feeding mH2 nodes -> bX1 (coef = val*diag1) + mark mT1
__global__ void __launch_bounds__(256) k_s3(const int* __restrict__ wiRows,
        const int* __restrict__ wiCols, const float* __restrict__ wiVals,
        const float* __restrict__ diag1, const float* __restrict__ x) {
    if (blockIdx.x >= SCAN_B) { xh_block(blockIdx.x - SCAN_B + 2 * XH_CHUNK, x); return; }
    int t = blockIdx.x * 256 + threadIdx.x;
    if (t >= SCAN_T) return;
    int base = t * 8;
    int4 a = __ldg((const int4*)(wiRows + base));
    int4 b4 = __ldg((const int4*)(wiRows + base + 4));
    int r[8] = {a.x, a.y, a.z, a.w, b4.x, b4.y, b4.z, b4.w};
    unsigned bl[8];
#pragma unroll
    for (int j = 0; j < 8; j++) bl[j] = __ldg(&g_blH2[(r[j] >> 5) & (BLH2_W - 1)]);
#pragma unroll
    for (int j = 0; j < 8; j++) {
        if ((bl[j] >> (r[j] & 31)) & 1u) {
            if ((__ldg(&g_mH2[r[j] >> 5]) >> (r[j] & 31)) & 1u) {
                int e = base + j;
                int col = __ldg(&wiCols[e]);
                float coef = __ldg(&wiVals[e]) * __ldg(&diag1[col]);
                int slot = atomicAdd(&g_cntX1[r[j]], 1);
                if (slot < CAP_X1)
                    g_bX1[r[j] * CAP_X1 + slot] = make_int2(col, __float_as_int(coef));
                atomicOr(&g_mT1[col >> 5], 1u << (col & 31));
            }
        }
    }
}

// S4: w-edges feeding mT1 rows -> bT1 (28% hit: stream cols+vals unconditionally)
__global__ void __launch_bounds__(256) k_s4(const int* __restrict__ wRows,
        const int* __restrict__ wCols, const float* __restrict__ wVals,
        const float* __restrict__ x) {
    if (blockIdx.x >= SCAN_B) { xh_block(blockIdx.x - SCAN_B + 3 * XH_CHUNK, x); return; }
    int t = blockIdx.x * 256 + threadIdx.x;
    if (t >= SCAN_T) return;
    int base = t * 8;
    int4 a = __ldg((const int4*)(wRows + base));
    int4 b4 = __ldg((const int4*)(wRows + base + 4));
    int4 c0 = __ldg((const int4*)(wCols + base));
    int4 c1 = __ldg((const int4*)(wCols + base + 4));
    float4 v0 = __ldg((const float4*)(wVals + base));
    float4 v1 = __ldg((const float4*)(wVals + base + 4));
    int r[8] = {a.x, a.y, a.z, a.w, b4.x, b4.y, b4.z, b4.w};
    int cc[8] = {c0.x, c0.y, c0.z, c0.w, c1.x, c1.y, c1.z, c1.w};
    float vv[8] = {v0.x, v0.y, v0.z, v0.w, v1.x, v1.y, v1.z, v1.w};
    unsigned m[8];
#pragma unroll
    for (int j = 0; j < 8; j++) m[j] = __ldg(&g_mT1[r[j] >> 5]);
#pragma unroll
    for (int j = 0; j < 8; j++) {
        if ((m[j] >> (r[j] & 31)) & 1u) {
            int slot = atomicAdd(&g_cntT1[r[j]], 1);
            if (slot < CAP_T1)
                g_bT1[r[j] * CAP_T1 + slot] = make_int2(cc[j], __float_as_int(vv[j]));
        }
    }
}

// ---------------- T1[row] = (sum_e v_e * x[col_e]) @ W1; one warp per row ------------
__global__ void __launch_bounds__(256) k_T1(const float* __restrict__ W1) {
    __shared__ float sW[D1 * D1];          // 4 KB (lazy-loaded)
    __shared__ float sA[8][BB * 36];       // padded stage: stride 36 -> conflict-free
    int w = (blockIdx.x * 256 + threadIdx.x) >> 5;
    int lane = threadIdx.x & 31;
    int c = 0;
    if (w < RR) { c = g_cntT1[w]; if (c > CAP_T1) c = CAP_T1; }
    int act = __syncthreads_or(c != 0);
    if (!act) return;                      // whole block inactive: skip sW load
    for (int i = threadIdx.x; i < D1 * D1; i += 256) sW[i] = W1[i];
    __syncthreads();
    if (c == 0) return;
    int b = lane >> 3, q = lane & 7;
    const int2* bk = &g_bT1[w * CAP_T1];
    float4 acc = make_float4(0.f, 0.f, 0.f, 0.f);
    int k = 0;
    for (; k + 4 <= c; k += 4) {
        int2 e0 = __ldg(&bk[k]),     e1 = __ldg(&bk[k + 1]);
        int2 e2 = __ldg(&bk[k + 2]), e3 = __ldg(&bk[k + 3]);
        uint2 u0 = *(const uint2*)&g_xh[((size_t)e0.x * BB + b) * D1 + q * 4];
        uint2 u1 = *(const uint2*)&g_xh[((size_t)e1.x * BB + b) * D1 + q * 4];
        uint2 u2 = *(const uint2*)&g_xh[((size_t)e2.x * BB + b) * D1 + q * 4];
        uint2 u3 = *(const uint2*)&g_xh[((size_t)e3.x * BB + b) * D1 + q * 4];
        float v0 = __int_as_float(e0.y), v1 = __int_as_float(e1.y);
        float v2 = __int_as_float(e2.y), v3 = __int_as_float(e3.y);
        float2 a01, a23;
        a01 = __half22float2(*(__half2*)&u0.x); a23 = __half22float2(*(__half2*)&u0.y);
        acc.x = fmaf(v0, a01.x, acc.x); acc.y = fmaf(v0, a01.y, acc.y);
        acc.z = fmaf(v0, a23.x, acc.z); acc.w = fmaf(v0, a23.y, acc.w);
        a01 = __half22float2(*(__half2*)&u1.x); a23 = __half22float2(*(__half2*)&u1.y);
        acc.x = fmaf(v1, a01.x, acc.x); acc.y = fmaf(v1, a01.y, acc.y);
        acc.z = fmaf(v1, a23.x, acc.z); acc.w = fmaf(v1, a23.y, acc.w);
        a01 = __half22float2(*(__half2*)&u2.x); a23 = __half22float2(*(__half2*)&u2.y);
        acc.x = fmaf(v2, a01.x, acc.x); acc.y = fmaf(v2, a01.y, acc.y);
        acc.z = fmaf(v2, a23.x, acc.z); acc.w = fmaf(v2, a23.y, acc.w);
        a01 = __half22float2(*(__half2*)&u3.x); a23 = __half22float2(*(__half2*)&u3.y);
        acc.x = fmaf(v3, a01.x, acc.x); acc.y = fmaf(v3, a01.y, acc.y);
        acc.z = fmaf(v3, a23.x, acc.z); acc.w = fmaf(v3, a23.y, acc.w);
    }
    for (; k < c; k++) {
        int2 e0 = __ldg(&bk[k]);
        float v = __int_as_float(e0.y);
        uint2 u0 = *(const uint2*)&g_xh[((size_t)e0.x * BB + b) * D1 + q * 4];
        float2 a01 = __half22float2(*(__half2*)&u0.x);
        float2 a23 = __half22float2(*(__half2*)&u0.y);
        acc.x = fmaf(v, a01.x, acc.x); acc.y = fmaf(v, a01.y, acc.y);
        acc.z = fmaf(v, a23.x, acc.z); acc.w = fmaf(v, a23.y, acc.w);
    }
    // transform: T1row[b][j] = sum_k xacc[b][k] * W1[k][j]
    int wl = threadIdx.x >> 5;
    *(float4*)&sA[wl][b * 36 + q * 4] = acc;
    __syncwarp();
    const float* xa = &sA[wl][b * 36];
    float4 o = make_float4(0.f, 0.f, 0.f, 0.f);
#pragma unroll
    for (int kk = 0; kk < D1; kk++) {
        float xk = xa[kk];
        float4 wr = *(const float4*)&sW[kk * D1 + q * 4];
        o.x = fmaf(xk, wr.x, o.x); o.y = fmaf(xk, wr.y, o.y);
        o.z = fmaf(xk, wr.z, o.z); o.w = fmaf(xk, wr.w, o.w);
    }
    *(float4*)&g_T1[((size_t)w * BB + b) * D1 + q * 4] = o;
}

// ---------------- fused x1 + h2, one warp per node, full width -----------------------
__global__ void __launch_bounds__(256) k_x1h2(const float* __restrict__ W2) {
    __shared__ float sW[D1 * D2];
    __shared__ float sX[8][BB * D1];
    int t = threadIdx.x;
    for (int i = t; i < D1 * D2; i += 256) sW[i] = W2[i];
    __syncthreads();
    int node = (blockIdx.x * 256 + t) >> 5;
    if (node >= NN) return;
    int c = g_cntX1[node];
    if (c == 0) return;
    if (c > CAP_X1) c = CAP_X1;
    int lane = t & 31;
    int wlocal = t >> 5;
    int b = lane >> 3, q = lane & 7;
    const int2* bk = &g_bX1[node * CAP_X1];
    float4 acc = make_float4(0.f, 0.f, 0.f, 0.f);
    int k = 0;
    for (; k + 2 <= c; k += 2) {
        int2 e0 = __ldg(&bk[k]), e1 = __ldg(&bk[k + 1]);
        float4 t0 = *(const float4*)&g_T1[((size_t)e0.x * BB + b) * D1 + q * 4];
        float4 t1 = *(const float4*)&g_T1[((size_t)e1.x * BB + b) * D1 + q * 4];
        float v0 = __int_as_float(e0.y), v1 = __int_as_float(e1.y);
        acc.x = fmaf(v0, t0.x, acc.x); acc.y = fmaf(v0, t0.y, acc.y);
        acc.z = fmaf(v0, t0.z, acc.z); acc.w = fmaf(v0, t0.w, acc.w);
        acc.x = fmaf(v1, t1.x, acc.x); acc.y = fmaf(v1, t1.y, acc.y);
        acc.z = fmaf(v1, t1.z, acc.z); acc.w = fmaf(v1, t1.w, acc.w);
    }
    for (; k < c; k++) {
        int2 e0 = __ldg(&bk[k]);
        float v = __int_as_float(e0.y);
        float4 tv = *(const float4*)&g_T1[((size_t)e0.x * BB + b) * D1 + q * 4];
        acc.x = fmaf(v, tv.x, acc.x); acc.y = fmaf(v, tv.y, acc.y);
        acc.z = fmaf(v, tv.z, acc.z); acc.w = fmaf(v, tv.w, acc.w);
    }
    acc.x = acc.x > 0.f ? acc.x : NEG * acc.x;
    acc.y = acc.y > 0.f ? acc.y : NEG * acc.y;
    acc.z = acc.z > 0.f ? acc.z : NEG * acc.z;
    acc.w = acc.w > 0.f ? acc.w : NEG * acc.w;
    *(float4*)&sX[wlocal][b * D1 + q * 4] = acc;
    __syncwarp();
    int j = lane & 7;
    const float* xr = &sX[wlocal][b * D1];
    float a0 = 0.f, a1 = 0.f;
#pragma unroll
    for (int kk = 0; kk < D1; kk++) {
        float xv = xr[kk];
        a0 = fmaf(xv, sW[kk * D2 + j], a0);
        a1 = fmaf(xv, sW[kk * D2 + j + 8], a1);
    }
    g_h2[((size_t)node * BB + b) * D2 + j] = a0;
    g_h2[((size_t)node * BB + b) * D2 + j + 8] = a1;
}

// ---------------- T2[row] = sum_e v_e * h2[col_e]; one warp per row, full width ------
__global__ void __launch_bounds__(256) k_T2() {
    int w = (blockIdx.x * 256 + threadIdx.x) >> 5;
    if (w >= RR) return;
    int c = g_cntT2[w];
    if (c == 0) return;
    if (c > CAP_T2) c = CAP_T2;
    int lane = threadIdx.x & 31;
    if (lane >= 16) return;
    int b = lane >> 2, q = lane & 3;
    const int2* bk = &g_bT2[w * CAP_T2];
    float4 acc = make_float4(0.f, 0.f, 0.f, 0.f);
    for (int k = 0; k < c; k++) {
        int2 e0 = __ldg(&bk[k]);
        float v = __int_as_float(e0.y);
        float4 h = *(const float4*)&g_h2[((size_t)e0.x * BB + b) * D2 + q * 4];
        acc.x = fmaf(v, h.x, acc.x); acc.y = fmaf(v, h.y, acc.y);
        acc.z = fmaf(v, h.z, acc.z); acc.w = fmaf(v, h.w, acc.w);
    }
    *(float4*)&g_T2[((size_t)w * BB + b) * D2 + q * 4] = acc;
}

// ---------------- final heads (4-way parallel) + tail zeroing ------------------------
__global__ void __launch_bounds__(1024) k_outz(const float* __restrict__ rw1,
        const float* __restrict__ rb1, const float* __restrict__ rw2,
        const float* __restrict__ rb2, float* __restrict__ out) {
    if (blockIdx.x == 0) {
        __shared__ float sP[8][4][16];
        int wrp = threadIdx.x >> 5, lane = threadIdx.x & 31;
        int p = wrp >> 2, part = wrp & 3;   // p in [0,8): s = p&1, b = p>>1
        int s = p & 1, b = p >> 1;
        int c = g_cntP1[s]; if (c > CAP_P1) c = CAP_P1;
        float acc = 0.f;
        for (int i = part; i < c; i += 4) {
            int2 e = g_bP1[s * CAP_P1 + i];
            float coef = __int_as_float(e.y);
            if (lane < D2) acc = fmaf(coef, g_T2[((size_t)e.x * BB + b) * D2 + lane], acc);
        }
        if (lane < D2) sP[p][part][lane] = acc;
        __syncthreads();
        if (part == 0 && lane < D2) {
            float v = sP[p][0][lane] + sP[p][1][lane] + sP[p][2][lane] + sP[p][3][lane];
            v = v > 0.f ? v : NEG * v;
            const float* rw = s ? rw2 : rw1;
            sP[p][0][lane] = v * rw[lane];
        }
        __syncthreads();
        if (threadIdx.x < 8) {
            int pp = threadIdx.x;
            int ss = pp & 1, bb = pp >> 1;
            float y = 0.f;
#pragma unroll
            for (int d = 0; d < D2; d++) y += sP[pp][0][d];
            out[bb * 2 + ss] = y + (ss ? rb2[0] : rb1[0]);
        }
        __syncthreads();   // everyone done reading g_cntP1 / blooms
        if (threadIdx.x < 2) g_cntP1[threadIdx.x] = 0;
        if (threadIdx.x >= 32 && threadIdx.x < 32 + BLT2_W) g_blT2[threadIdx.x - 32] = 0u;
    } else {
        int i0 = (blockIdx.x - 1) * 1024 + threadIdx.x;
        const int stride = 16 * 1024;
        for (int i = i0; i < RR; i += stride) { g_cntT1[i] = 0; g_cntT2[i] = 0; }
        for (int i = i0; i < NN; i += stride) g_cntX1[i] = 0;
        for (int i = i0; i < MW_R; i += stride) { g_mT1[i] = 0u; g_mT2[i] = 0u; }
        for (int i = i0; i < MW_N; i += stride) g_mH2[i] = 0u;
        for (int i = i0; i < BLH2_W; i += stride) g_blH2[i] = 0u;
    }
}

// ---------------- launch ----------------
extern "C" void kernel_launch(void* const* d_in, const int* in_sizes, int n_in,
                              void* d_out, int out_size) {
    const int*   wIdx   = (const int*)d_in[0];
    const float* wVal   = (const float*)d_in[1];
    const int*   wiIdx  = (const int*)d_in[2];
    const float* wiVal  = (const float*)d_in[3];
    const float* x      = (const float*)d_in[4];
    const float* W1     = (const float*)d_in[5];
    const float* diag1  = (const float*)d_in[6];
    const float* W2     = (const float*)d_in[7];
    const float* diag2  = (const float*)d_in[8];
    const float* rw1    = (const float*)d_in[9];
    const float* rb1    = (const float*)d_in[10];
    const float* rw2    = (const float*)d_in[11];
    const float* rb2    = (const float*)d_in[12];

    const int* wRows  = wIdx;
    const int* wCols  = wIdx + EE;
    const int* wiRows = wiIdx;
    const int* wiCols = wiIdx + EE;
    float* out = (float*)d_out;

    const int mixGrid = SCAN_B + XH_CHUNK;   // 782 + 6250 (R10 layout, lighter freight)

    k_s1<<<mixGrid, 256>>>(wiRows, wiCols, wiVal, diag2, x);
    k_s2<<<mixGrid, 256>>>(wRows, wCols, wVal, x);
    k_s3<<<mixGrid, 256>>>(wiRows, wiCols, wiVal, diag1, x);
    k_s4<<<mixGrid, 256>>>(wRows, wCols, wVal, x);
    k_T1<<<(RR * 32 + 255) / 256, 256>>>(W1);
    k_x1h2<<<(NN * 32 + 255) / 256, 256>>>(W2);
    k_T2<<<(RR * 32 + 255) / 256, 256>>>();
    k_outz<<<17, 1024>>>(rw1, rb1, rw2, rb2, out);
}

// round 17
// speedup vs baseline: 1.7471x; 1.1230x over previous
#include <cuda_runtime.h>
#include <cuda_fp16.h>
#include <cstdint>

// Problem constants (fixed by the dataset)
#define BB 4
#define NN 50000
#define RR 100000
#define EE 1600000
#define D1 32
#define D2 16
#define NEG 0.2f

// Bucket capacities (Poisson lambda=16 R-rows / 32 N-rows; overflow prob < 1e-25)
#define CAP_T1 128
#define CAP_X1 192
#define CAP_T2 128
#define CAP_P1 256

#define MW_R ((RR + 31) / 32)
#define MW_N ((NN + 31) / 32)

#define SCAN_T   (EE / 8)                  // 200000 scan threads (8 edges each)
#define SCAN_B   ((SCAN_T + 255) / 256)    // 782 scan blocks
#define XH_W     (NN * BB)                 // 200000 conversion rows (one warp each)
#define XH_B     ((XH_W + 7) / 8)          // 25000 freight blocks (8 warps/block)
#define XH_CHUNK (XH_B / 4)                // 6250 freight blocks per scan kernel

// Bloom filters (first-level membership pre-check; tiny -> L1-broadcast loads)
#define BLT2_W 64     // 256 B, 2048 bits   (~64 set -> FP 3%)
#define BLH2_W 256    // 1 KB, 8192 bits    (~1K set -> FP 12%)

// ---------------- device scratch (zero-init at module load; left zeroed per call) ----
__device__ __half g_xh[NN * BB * D1];   // 12.8 MB  [n][b][32] fp16 copy of x
__device__ __half g_T1[RR * BB * D1];   // 25.6 MB  [r][b][32] fp16 RAW x-accum (pre-W1)
__device__ float g_h2[NN * BB * D2];    // 12.8 MB  [n][b][16]
__device__ float g_T2[RR * BB * D2];    // 25.6 MB  [r][b][16]

__device__ int  g_cntT1[RR], g_cntX1[NN], g_cntT2[RR], g_cntP1[2];
__device__ int2 g_bT1[RR * CAP_T1];    // (col, val)
__device__ int2 g_bX1[NN * CAP_X1];    // (col, coef)
__device__ int2 g_bT2[RR * CAP_T2];    // (col, val)
__device__ int2 g_bP1[2 * CAP_P1];     // (col, coef)

__device__ unsigned g_mT1[MW_R], g_mT2[MW_R], g_mH2[MW_N];   // exact bit flags
__device__ unsigned g_blT2[BLT2_W], g_blH2[BLH2_W];          // bloom pre-filters
__device__ int g_listX1[NN], g_listT2[RR];                   // tiny active lists
__device__ int g_nX1, g_nT2;

// ---------------- freight: xh[n][b][:] = fp16(x[b][n][:]); 1 LDG + 1 STG per warp ----
__device__ __forceinline__ void xh_block(int vb, const float* __restrict__ x) {
    int w = vb * 8 + (threadIdx.x >> 5);
    if (w >= XH_W) return;
    int lane = threadIdx.x & 31;
    int n = w >> 2, b = w & 3;
    float xv = __ldg(&x[((size_t)b * NN + n) * D1 + lane]);
    g_xh[(size_t)w * D1 + lane] = __float2half(xv);
}

// ---------------- scan kernels: scan blocks first, then a conversion chunk -----------
// S1: wi-edges into the 2 output nodes -> bP1 + mark mT2 + bloom blT2
__global__ void __launch_bounds__(256) k_s1(const int* __restrict__ wiRows,
        const int* __restrict__ wiCols, const float* __restrict__ wiVals,
        const float* __restrict__ diag2, const float* __restrict__ x) {
    if (blockIdx.x >= SCAN_B) { xh_block(blockIdx.x - SCAN_B, x); return; }
    int t = blockIdx.x * 256 + threadIdx.x;
    if (t >= SCAN_T) return;
    int base = t * 8;
    int4 a = __ldg((const int4*)(wiRows + base));
    int4 b4 = __ldg((const int4*)(wiRows + base + 4));
    int r[8] = {a.x, a.y, a.z, a.w, b4.x, b4.y, b4.z, b4.w};
#pragma unroll
    for (int j = 0; j < 8; j++) {
        if (r[j] >= NN - 2) {
            int s = r[j] - (NN - 2);
            int e = base + j;
            int col = __ldg(&wiCols[e]);
            float coef = __ldg(&wiVals[e]) * __ldg(&diag2[col]);
            int slot = atomicAdd(&g_cntP1[s], 1);
            if (slot < CAP_P1) g_bP1[s * CAP_P1 + slot] = make_int2(col, __float_as_int(coef));
            atomicOr(&g_mT2[col >> 5], 1u << (col & 31));
            atomicOr(&g_blT2[(col >> 5) & (BLT2_W - 1)], 1u << (col & 31));
        }
    }
}

// S2: w-edges feeding mT2 rows -> bT2 + mark mH2 + bloom blH2 + listT2 (~64 appends)
__global__ void __launch_bounds__(256) k_s2(const int* __restrict__ wRows,
        const int* __restrict__ wCols, const float* __restrict__ wVals,
        const float* __restrict__ x) {
    if (blockIdx.x >= SCAN_B) { xh_block(blockIdx.x - SCAN_B + XH_CHUNK, x); return; }
    int t = blockIdx.x * 256 + threadIdx.x;
    if (t >= SCAN_T) return;
    int base = t * 8;
    int4 a = __ldg((const int4*)(wRows + base));
    int4 b4 = __ldg((const int4*)(wRows + base + 4));
    int r[8] = {a.x, a.y, a.z, a.w, b4.x, b4.y, b4.z, b4.w};
    unsigned bl[8];
#pragma unroll
    for (int j = 0; j < 8; j++) bl[j] = __ldg(&g_blT2[(r[j] >> 5) & (BLT2_W - 1)]);
#pragma unroll
    for (int j = 0; j < 8; j++) {
        if ((bl[j] >> (r[j] & 31)) & 1u) {
            if ((__ldg(&g_mT2[r[j] >> 5]) >> (r[j] & 31)) & 1u) {
                int e = base + j;
                int col = __ldg(&wCols[e]);
                int slot = atomicAdd(&g_cntT2[r[j]], 1);
                if (slot == 0) g_listT2[atomicAdd(&g_nT2, 1)] = r[j];
                if (slot < CAP_T2)
                    g_bT2[r[j] * CAP_T2 + slot] = make_int2(col, __float_as_int(__ldg(&wVals[e])));
                atomicOr(&g_mH2[col >> 5], 1u << (col & 31));
                atomicOr(&g_blH2[(col >> 5) & (BLH2_W - 1)], 1u << (col & 31));
            }
        }
    }
}

// S3: wi-edges feeding mH2 nodes -> bX1 (coef = val*diag1) + mark mT1 + listX1 (~1K)
__global__ void __launch_bounds__(256) k_s3(const int* __restrict__ wiRows,
        const int* __restrict__ wiCols, const float* __restrict__ wiVals,
        const float* __restrict__ diag1, const float* __restrict__ x) {
    if (blockIdx.x >= SCAN_B) { xh_block(blockIdx.x - SCAN_B + 2 * XH_CHUNK, x); return; }
    int t = blockIdx.x * 256 + threadIdx.x;
    if (t >= SCAN_T) return;
    int base = t * 8;
    int4 a = __ldg((const int4*)(wiRows + base));
    int4 b4 = __ldg((const int4*)(wiRows + base + 4));
    int r[8] = {a.x, a.y, a.z, a.w, b4.x, b4.y, b4.z, b4.w};
    unsigned bl[8];
#pragma unroll
    for (int j = 0; j < 8; j++) bl[j] = __ldg(&g_blH2[(r[j] >> 5) & (BLH2_W - 1)]);
#pragma unroll
    for (int j = 0; j < 8; j++) {
        if ((bl[j] >> (r[j] & 31)) & 1u) {
            if ((__ldg(&g_mH2[r[j] >> 5]) >> (r[j] & 31)) & 1u) {
                int e = base + j;
                int col = __ldg(&wiCols[e]);
                float coef = __ldg(&wiVals[e]) * __ldg(&diag1[col]);
                int slot = atomicAdd(&g_cntX1[r[j]], 1);
                if (slot == 0) g_listX1[atomicAdd(&g_nX1, 1)] = r[j];
                if (slot < CAP_X1)
                    g_bX1[r[j] * CAP_X1 + slot] = make_int2(col, __float_as_int(coef));
                atomicOr(&g_mT1[col >> 5], 1u << (col & 31));
            }
        }
    }
}

// S4: w-edges feeding mT1 rows -> bT1 (28% hit: stream cols+vals unconditionally)
__global__ void __launch_bounds__(256) k_s4(const int* __restrict__ wRows,
        const int* __restrict__ wCols, const float* __restrict__ wVals,
        const float* __restrict__ x) {
    if (blockIdx.x >= SCAN_B) { xh_block(blockIdx.x - SCAN_B + 3 * XH_CHUNK, x); return; }
    int t = blockIdx.x * 256 + threadIdx.x;
    if (t >= SCAN_T) return;
    int base = t * 8;
    int4 a = __ldg((const int4*)(wRows + base));
    int4 b4 = __ldg((const int4*)(wRows + base + 4));
    int4 c0 = __ldg((const int4*)(wCols + base));
    int4 c1 = __ldg((const int4*)(wCols + base + 4));
    float4 v0 = __ldg((const float4*)(wVals + base));
    float4 v1 = __ldg((const float4*)(wVals + base + 4));
    int r[8] = {a.x, a.y, a.z, a.w, b4.x, b4.y, b4.z, b4.w};
    int cc[8] = {c0.x, c0.y, c0.z, c0.w, c1.x, c1.y, c1.z, c1.w};
    float vv[8] = {v0.x, v0.y, v0.z, v0.w, v1.x, v1.y, v1.z, v1.w};
    unsigned m[8];
#pragma unroll
    for (int j = 0; j < 8; j++) m[j] = __ldg(&g_mT1[r[j] >> 5]);
#pragma unroll
    for (int j = 0; j < 8; j++) {
        if ((m[j] >> (r[j] & 31)) & 1u) {
            int slot = atomicAdd(&g_cntT1[r[j]], 1);
            if (slot < CAP_T1)
                g_bT1[r[j] * CAP_T1 + slot] = make_int2(cc[j], __float_as_int(vv[j]));
        }
    }
}

// ---------------- T1raw[row] = sum_e v_e * xh[col_e]; fp16 store, no transform -------
__global__ void __launch_bounds__(256) k_T1() {
    int w = (blockIdx.x * 256 + threadIdx.x) >> 5;
    if (w >= RR) return;
    int c = g_cntT1[w];
    if (c == 0) return;
    if (c > CAP_T1) c = CAP_T1;
    int lane = threadIdx.x & 31;
    int b = lane >> 3, q = lane & 7;
    const int2* bk = &g_bT1[w * CAP_T1];
    float4 acc = make_float4(0.f, 0.f, 0.f, 0.f);
    int k = 0;
    for (; k + 4 <= c; k += 4) {
        int2 e0 = __ldg(&bk[k]),     e1 = __ldg(&bk[k + 1]);
        int2 e2 = __ldg(&bk[k + 2]), e3 = __ldg(&bk[k + 3]);
        uint2 u0 = *(const uint2*)&g_xh[((size_t)e0.x * BB + b) * D1 + q * 4];
        uint2 u1 = *(const uint2*)&g_xh[((size_t)e1.x * BB + b) * D1 + q * 4];
        uint2 u2 = *(const uint2*)&g_xh[((size_t)e2.x * BB + b) * D1 + q * 4];
        uint2 u3 = *(const uint2*)&g_xh[((size_t)e3.x * BB + b) * D1 + q * 4];
        float v0 = __int_as_float(e0.y), v1 = __int_as_float(e1.y);
        float v2 = __int_as_float(e2.y), v3 = __int_as_float(e3.y);
        float2 a01, a23;
        a01 = __half22float2(*(__half2*)&u0.x); a23 = __half22float2(*(__half2*)&u0.y);
        acc.x = fmaf(v0, a01.x, acc.x); acc.y = fmaf(v0, a01.y, acc.y);
        acc.z = fmaf(v0, a23.x, acc.z); acc.w = fmaf(v0, a23.y, acc.w);
        a01 = __half22float2(*(__half2*)&u1.x); a23 = __half22float2(*(__half2*)&u1.y);
        acc.x = fmaf(v1, a01.x, acc.x); acc.y = fmaf(v1, a01.y, acc.y);
        acc.z = fmaf(v1, a23.x, acc.z); acc.w = fmaf(v1, a23.y, acc.w);
        a01 = __half22float2(*(__half2*)&u2.x); a23 = __half22float2(*(__half2*)&u2.y);
        acc.x = fmaf(v2, a01.x, acc.x); acc.y = fmaf(v2, a01.y, acc.y);
        acc.z = fmaf(v2, a23.x, acc.z); acc.w = fmaf(v2, a23.y, acc.w);
        a01 = __half22float2(*(__half2*)&u3.x); a23 = __half22float2(*(__half2*)&u3.y);
        acc.x = fmaf(v3, a01.x, acc.x); acc.y = fmaf(v3, a01.y, acc.y);
        acc.z = fmaf(v3, a23.x, acc.z); acc.w = fmaf(v3, a23.y, acc.w);
    }
    for (; k < c; k++) {
        int2 e0 = __ldg(&bk[k]);
        float v = __int_as_float(e0.y);
        uint2 u0 = *(const uint2*)&g_xh[((size_t)e0.x * BB + b) * D1 + q * 4];
        float2 a01 = __half22float2(*(__half2*)&u0.x);
        float2 a23 = __half22float2(*(__half2*)&u0.y);
        acc.x = fmaf(v, a01.x, acc.x); acc.y = fmaf(v, a01.y, acc.y);
        acc.z = fmaf(v, a23.x, acc.z); acc.w = fmaf(v, a23.y, acc.w);
    }
    uint2 st;
    *(__half2*)&st.x = __float22half2_rn(make_float2(acc.x, acc.y));
    *(__half2*)&st.y = __float22half2_rn(make_float2(acc.z, acc.w));
    *(uint2*)&g_T1[((size_t)w * BB + b) * D1 + q * 4] = st;
}

// ---------------- fused x1 + h2 over active nodes (listX1): gather, @W1, leaky, @W2 --
__global__ void __launch_bounds__(256) k_x1h2(const float* __restrict__ W1,
                                              const float* __restrict__ W2) {
    __shared__ float sW1[D1 * D1];          // 4 KB
    __shared__ float sW2[D1 * D2];          // 2 KB
    __shared__ float sA[8][BB * 36];        // raw accum stage (pad 36)
    __shared__ float sX[8][BB * D1];        // x1 stage
    int t = threadIdx.x;
    for (int i = t; i < D1 * D1; i += 256) sW1[i] = W1[i];
    for (int i = t; i < D1 * D2; i += 256) sW2[i] = W2[i];
    __syncthreads();
    int lane = t & 31, wl = t >> 5;
    int gw = blockIdx.x * 8 + wl, nw = gridDim.x * 8;
    int b = lane >> 3, q = lane & 7;
    int nact = g_nX1;
    for (int i = gw; i < nact; i += nw) {
        int node = g_listX1[i];
        int c = g_cntX1[node]; if (c > CAP_X1) c = CAP_X1;
        const int2* bk = &g_bX1[node * CAP_X1];
        float4 acc = make_float4(0.f, 0.f, 0.f, 0.f);
        int k = 0;
        for (; k + 2 <= c; k += 2) {
            int2 e0 = __ldg(&bk[k]), e1 = __ldg(&bk[k + 1]);
            uint2 u0 = *(const uint2*)&g_T1[((size_t)e0.x * BB + b) * D1 + q * 4];
            uint2 u1 = *(const uint2*)&g_T1[((size_t)e1.x * BB + b) * D1 + q * 4];
            float v0 = __int_as_float(e0.y), v1 = __int_as_float(e1.y);
            float2 a01, a23;
            a01 = __half22float2(*(__half2*)&u0.x); a23 = __half22float2(*(__half2*)&u0.y);
            acc.x = fmaf(v0, a01.x, acc.x); acc.y = fmaf(v0, a01.y, acc.y);
            acc.z = fmaf(v0, a23.x, acc.z); acc.w = fmaf(v0, a23.y, acc.w);
            a01 = __half22float2(*(__half2*)&u1.x); a23 = __half22float2(*(__half2*)&u1.y);
            acc.x = fmaf(v1, a01.x, acc.x); acc.y = fmaf(v1, a01.y, acc.y);
            acc.z = fmaf(v1, a23.x, acc.z); acc.w = fmaf(v1, a23.y, acc.w);
        }
        for (; k < c; k++) {
            int2 e0 = __ldg(&bk[k]);
            float v = __int_as_float(e0.y);
            uint2 u0 = *(const uint2*)&g_T1[((size_t)e0.x * BB + b) * D1 + q * 4];
            float2 a01 = __half22float2(*(__half2*)&u0.x);
            float2 a23 = __half22float2(*(__half2*)&u0.y);
            acc.x = fmaf(v, a01.x, acc.x); acc.y = fmaf(v, a01.y, acc.y);
            acc.z = fmaf(v, a23.x, acc.z); acc.w = fmaf(v, a23.y, acc.w);
        }
        // apply W1: x1[b][j] = leaky( sum_k M[b][k] * W1[k][j] )
        *(float4*)&sA[wl][b * 36 + q * 4] = acc;
        __syncwarp();
        const float* xa = &sA[wl][b * 36];
        float4 o = make_float4(0.f, 0.f, 0.f, 0.f);
#pragma unroll
        for (int kk = 0; kk < D1; kk++) {
            float xk = xa[kk];
            float4 wr = *(const float4*)&sW1[kk * D1 + q * 4];
            o.x = fmaf(xk, wr.x, o.x); o.y = fmaf(xk, wr.y, o.y);
            o.z = fmaf(xk, wr.z, o.z); o.w = fmaf(xk, wr.w, o.w);
        }
        o.x = o.x > 0.f ? o.x : NEG * o.x;
        o.y = o.y > 0.f ? o.y : NEG * o.y;
        o.z = o.z > 0.f ? o.z : NEG * o.z;
        o.w = o.w > 0.f ? o.w : NEG * o.w;
        *(float4*)&sX[wl][b * D1 + q * 4] = o;
        __syncwarp();
        // h2 = x1 @ W2
        int j = lane & 7;
        const float* xr = &sX[wl][b * D1];
        float a0 = 0.f, a1 = 0.f;
#pragma unroll
        for (int kk = 0; kk < D1; kk++) {
            float xv = xr[kk];
            a0 = fmaf(xv, sW2[kk * D2 + j], a0);
            a1 = fmaf(xv, sW2[kk * D2 + j + 8], a1);
        }
        g_h2[((size_t)node * BB + b) * D2 + j] = a0;
        g_h2[((size_t)node * BB + b) * D2 + j + 8] = a1;
        __syncwarp();
    }
}

// ---------------- T2 over active rows (listT2); one warp per row ---------------------
__global__ void __launch_bounds__(256) k_T2() {
    int lane = threadIdx.x & 31;
    int gw = blockIdx.x * 8 + (threadIdx.x >> 5), nw = gridDim.x * 8;
    int nact = g_nT2;
    int b = (lane >> 2) & 3, q = lane & 3;
    for (int i = gw; i < nact; i += nw) {
        int row = g_listT2[i];
        int c = g_cntT2[row]; if (c > CAP_T2) c = CAP_T2;
        if (lane >= 16) continue;
        const int2* bk = &g_bT2[row * CAP_T2];
        float4 acc = make_float4(0.f, 0.f, 0.f, 0.f);
        for (int k = 0; k < c; k++) {
            int2 e0 = __ldg(&bk[k]);
            float v = __int_as_float(e0.y);
            float4 h = *(const float4*)&g_h2[((size_t)e0.x * BB + b) * D2 + q * 4];
            acc.x = fmaf(v, h.x, acc.x); acc.y = fmaf(v, h.y, acc.y);
            acc.z = fmaf(v, h.z, acc.z); acc.w = fmaf(v, h.w, acc.w);
        }
        *(float4*)&g_T2[((size_t)row * BB + b) * D2 + q * 4] = acc;
    }
}

// ---------------- final heads (4-way parallel) + tail zeroing ------------------------
__global__ void __launch_bounds__(1024) k_outz(const float* __restrict__ rw1,
        const float* __restrict__ rb1, const float* __restrict__ rw2,
        const float* __restrict__ rb2, float* __restrict__ out) {
    if (blockIdx.x == 0) {
        __shared__ float sP[8][4][16];
        int wrp = threadIdx.x >> 5, lane = threadIdx.x & 31;
        int p = wrp >> 2, part = wrp & 3;   // p in [0,8): s = p&1, b = p>>1
        int s = p & 1, b = p >> 1;
        int c = g_cntP1[s]; if (c > CAP_P1) c = CAP_P1;
        float acc = 0.f;
        for (int i = part; i < c; i += 4) {
            int2 e = g_bP1[s * CAP_P1 + i];
            float coef = __int_as_float(e.y);
            if (lane < D2) acc = fmaf(coef, g_T2[((size_t)e.x * BB + b) * D2 + lane], acc);
        }
        if (lane < D2) sP[p][part][lane] = acc;
        __syncthreads();
        if (part == 0 && lane < D2) {
            float v = sP[p][0][lane] + sP[p][1][lane] + sP[p][2][lane] + sP[p][3][lane];
            v = v > 0.f ? v : NEG * v;
            const float* rw = s ? rw2 : rw1;
            sP[p][0][lane] = v * rw[lane];
        }
        __syncthreads();
        if (threadIdx.x < 8) {
            int pp = threadIdx.x;
            int ss = pp & 1, bb = pp >> 1;
            float y = 0.f;
#pragma unroll
            for (int d = 0; d < D2; d++) y += sP[pp][0][d];
            out[bb * 2 + ss] = y + (ss ? rb2[0] : rb1[0]);
        }
        __syncthreads();   // everyone done reading g_cntP1 / blooms / lists
        if (threadIdx.x < 2) g_cntP1[threadIdx.x] = 0;
        if (threadIdx.x == 2) g_nX1 = 0;
        if (threadIdx.x == 3) g_nT2 = 0;
        if (threadIdx.x >= 32 && threadIdx.x < 32 + BLT2_W) g_blT2[threadIdx.x - 32] = 0u;
    } else {
        int i0 = (blockIdx.x - 1) * 1024 + threadIdx.x;
        const int stride = 16 * 1024;
        for (int i = i0; i < RR; i += stride) { g_cntT1[i] = 0; g_cntT2[i] = 0; }
        for (int i = i0; i < NN; i += stride) g_cntX1[i] = 0;
        for (int i = i0; i < MW_R; i += stride) { g_mT1[i] = 0u; g_mT2[i] = 0u; }
        for (int i = i0; i < MW_N; i += stride) g_mH2[i] = 0u;
        for (int i = i0; i < BLH2_W; i += stride) g_blH2[i] = 0u;
    }
}

// ---------------- launch ----------------
extern "C" void kernel_launch(void* const* d_in, const int* in_sizes, int n_in,
                              void* d_out, int out_size) {
    const int*   wIdx   = (const int*)d_in[0];
    const float* wVal   = (const float*)d_in[1];
    const int*   wiIdx  = (const int*)d_in[2];
    const float* wiVal  = (const float*)d_in[3];
    const float* x      = (const float*)d_in[4];
    const float* W1     = (const float*)d_in[5];
    const float* diag1  = (const float*)d_in[6];
    const float* W2     = (const float*)d_in[7];
    const float* diag2  = (const float*)d_in[8];
    const float* rw1    = (const float*)d_in[9];
    const float* rb1    = (const float*)d_in[10];
    const float* rw2    = (const float*)d_in[11];
    const float* rb2    = (const float*)d_in[12];

    const int* wRows  = wIdx;
    const int* wCols  = wIdx + EE;
    const int* wiRows = wiIdx;
    const int* wiCols = wiIdx + EE;
    float* out = (float*)d_out;

    const int mixGrid = SCAN_B + XH_CHUNK;   // 782 + 6250

    k_s1<<<mixGrid, 256>>>(wiRows, wiCols, wiVal, diag2, x);
    k_s2<<<mixGrid, 256>>>(wRows, wCols, wVal, x);
    k_s3<<<mixGrid, 256>>>(wiRows, wiCols, wiVal, diag1, x);
    k_s4<<<mixGrid, 256>>>(wRows, wCols, wVal, x);
    k_T1<<<(RR * 32 + 255) / 256, 256>>>();
    k_x1h2<<<64, 256>>>(W1, W2);
    k_T2<<<8, 256>>>();
    k_outz<<<17, 1024>>>(rw1, rb1, rw2, rb2, out);
}